// round 13
// baseline (speedup 1.0000x reference)
#include <cuda_runtime.h>
#include <cuda_fp16.h>
#include <cstdint>
#include <math.h>

#define DI __device__ __forceinline__

constexpr int NN = 16384;
constexpr int STAGES = 5;
constexpr int KTILE = 64;
constexpr int NITER = NN / KTILE;                 // 256
constexpr int STAGE_BYTES = 24576;                // A fp16 8K (<=64 rows) + B fp16 16K
constexpr uint32_t SM_W = STAGES * STAGE_BYTES;   // 122880
constexpr uint32_t SM_BS = SM_W + 16384;          // 139264
constexpr uint32_t GEMM_SMEM = SM_BS + 512;       // 139776 (>114KB -> occ 1, intended)
constexpr uint32_t PREP_SMEM = 66048 + 16384;     // Es + W0T

// Inter-layer transposed feature panels (fp16): X?T[j][i] = X[i][j]
__device__ __half g_X0T[128 * NN];
__device__ __half g_X1T[128 * NN];

// ---------------------------------------------------------------- helpers
DI uint32_t smem_u32(const void* p) {
    uint32_t a;
    asm("{ .reg .u64 t; cvta.to.shared.u64 t, %1; cvt.u32.u64 %0, t; }" : "=r"(a) : "l"(p));
    return a;
}
DI uint32_t sw128(uint32_t b) { return b ^ ((b >> 3) & 0x70); }
DI float eluf(float x) { return x > 0.f ? x : expm1f(x); }

DI void cpa16(uint32_t s, const void* g) {
    asm volatile("cp.async.cg.shared.global [%0], [%1], 16;" :: "r"(s), "l"(g));
}
DI void ldsm4(uint32_t* r, uint32_t addr) {
    asm volatile("ldmatrix.sync.aligned.m8n8.x4.shared.b16 {%0,%1,%2,%3}, [%4];"
                 : "=r"(r[0]), "=r"(r[1]), "=r"(r[2]), "=r"(r[3]) : "r"(addr));
}
DI void mma16(float* d, const uint32_t* a, uint32_t b0, uint32_t b1) {
    asm volatile(
        "mma.sync.aligned.m16n8k16.row.col.f32.f16.f16.f32 "
        "{%0,%1,%2,%3}, {%4,%5,%6,%7}, {%8,%9}, {%0,%1,%2,%3};"
        : "+f"(d[0]), "+f"(d[1]), "+f"(d[2]), "+f"(d[3])
        : "r"(a[0]), "r"(a[1]), "r"(a[2]), "r"(a[3]), "r"(b0), "r"(b1));
}
DI uint32_t pack_h2(float lo, float hi) {
    __half2 h = __floats2half2_rn(lo, hi);
    return *reinterpret_cast<uint32_t*>(&h);
}

// ---------------------------------------------------------------- prep: X0T = [elu(zs)@W0 ; elu(zu)@W0]^T  (fp16)
__global__ void __launch_bounds__(512) prep_kernel(const float* __restrict__ z,
                                                   const float* __restrict__ W0,
                                                   __half* __restrict__ X0T) {
    extern __shared__ char smem[];
    float* Es = (float*)smem;            // [128][129] elu(z) rows
    float* Ws = (float*)(smem + 66048);  // [64][64]  W0^T: Ws[j][c] = W0[c][j]
    int tid = threadIdx.x;
    int m0 = blockIdx.x * 128;

    for (int e = tid; e < 128 * 128; e += 512) {
        int i = e >> 7, c = e & 127;
        Es[i * 129 + c] = eluf(z[(size_t)(m0 + i) * 128 + c]);
    }
    for (int e = tid; e < 64 * 64; e += 512) {
        int j = e >> 6, c = e & 63;
        Ws[j * 64 + c] = W0[c * 64 + j];
    }
    __syncthreads();

    int i = tid & 127;
    int part = tid >> 7;          // 0..3
    int ho = (part & 1) * 64;     // s/u half
    int j0 = (part >> 1) * 32;    // feature half
    float h[64];
#pragma unroll
    for (int c = 0; c < 64; c++) h[c] = Es[i * 129 + ho + c];
    for (int jj = j0; jj < j0 + 32; jj++) {
        const float4* wr = (const float4*)(Ws + jj * 64);
        float acc = 0.f;
#pragma unroll
        for (int q = 0; q < 16; q++) {
            float4 w = wr[q];
            acc += h[4 * q] * w.x + h[4 * q + 1] * w.y + h[4 * q + 2] * w.z + h[4 * q + 3] * w.w;
        }
        X0T[(size_t)(ho + jj) * NN + m0 + i] = __float2half_rn(acc);
    }
}

// ---------------------------------------------------------------- GEMM body for one M-unit (MROWS = 64 or 48)
// 512 threads = 16 warps; wm = wid>>2 (M frag row), wn = wid&3 (N group of 32).
// Warps with wm*16 >= MROWS skip MMA (evenly spread across SMSPs) but help staging.
template <int PASS, int MROWS>
DI void gemm_body(const float* __restrict__ adj, const __half* __restrict__ BT,
                  const float* __restrict__ bias, const float* __restrict__ W2,
                  const float* __restrict__ bl, float* __restrict__ OUT,
                  __half* __restrict__ OUTH, int m_start, char* smem, uint32_t sb) {
    int tid = threadIdx.x, wid = tid >> 5, lane = tid & 31;

    // preload epilogue weights + bias (region disjoint from stages)
    {
        float* Wsm = (float*)(smem + SM_W);
        if (PASS == 1) {
            for (int e = tid; e < 64 * 64; e += 512)        // W1^T: Wsm[j*64+c]=W1[c][j]
                Wsm[e] = W2[(e & 63) * 64 + (e >> 6)];
        } else {
            for (int e = tid; e < 128 * 32; e += 512)       // Wl^T: Wsm[j*32+o]=Wl[o][j]
                Wsm[e] = W2[(e & 31) * 128 + (e >> 5)];
        }
        float* bsm = (float*)(smem + SM_BS);
        if (tid < 128) bsm[tid] = bias[tid & 63];
    }

    // A staging (fp32->fp16): 8 threads/row, 8 floats each
    int arid = tid >> 3;                 // tile row 0..63
    int aseg = tid & 7;
    bool a_act = arid < MROWS;
    const float* agbase = adj + (size_t)(m_start + arid) * NN + aseg * 8;
    uint32_t ast = sw128((uint32_t)(arid * 128 + aseg * 16));

    // B staging: 2 x 16B chunks per thread (1024 chunks: r=chunk>>3, c=chunk&7)
    int bc0 = tid, bc1 = tid + 512;

    // warp fragment bases
    int wm = wid >> 2, wn = wid & 3;
    bool mma_act = (wm * 16) < MROWS;
    int n_off = wn * 32;
    int r8 = lane & 7;
    uint32_t arow = (uint32_t)((wm * 16 + r8 + ((lane >> 3) & 1) * 8) * 128);
    uint32_t acolsel = (uint32_t)(((lane >> 4) & 1) * 16);
    uint32_t brow[2];
#pragma unroll
    for (int p = 0; p < 2; p++)
        brow[p] = (uint32_t)((n_off + p * 16 + r8 + ((lane >> 4) & 1) * 8) * 128);
    uint32_t bcolsel = (uint32_t)(((lane >> 3) & 1) * 16);

    float acc[4][4];
#pragma unroll
    for (int nf = 0; nf < 4; nf++)
#pragma unroll
        for (int r = 0; r < 4; r++) acc[nf][r] = 0.f;

    // ---- prologue: stage tiles 0..STAGES-2
#pragma unroll
    for (int p = 0; p < STAGES - 1; p++) {
        uint32_t abo = (uint32_t)p * STAGE_BYTES;
        if (a_act) {
            const float* ag = agbase + (size_t)p * KTILE;
            float4 f0 = ((const float4*)ag)[0], f1 = ((const float4*)ag)[1];
            *(uint4*)(smem + abo + ast) =
                make_uint4(pack_h2(f0.x, f0.y), pack_h2(f0.z, f0.w),
                           pack_h2(f1.x, f1.y), pack_h2(f1.z, f1.w));
        }
        uint32_t bb = sb + abo + 8192;
        int r = bc0 >> 3, c = bc0 & 7;
        cpa16(bb + sw128((uint32_t)(r * 128 + c * 16)),
              BT + (size_t)r * NN + (size_t)p * KTILE + c * 8);
        r = bc1 >> 3; c = bc1 & 7;
        cpa16(bb + sw128((uint32_t)(r * 128 + c * 16)),
              BT + (size_t)r * NN + (size_t)p * KTILE + c * 8);
        asm volatile("cp.async.commit_group;" ::: "memory");
    }
    asm volatile("cp.async.wait_group %0;" :: "n"(STAGES - 2) : "memory");
    __syncthreads();

    // ---- mainloop
    for (int kt = 0; kt < NITER; kt++) {
        int kl = kt + STAGES - 1;
        uint32_t pslot = (uint32_t)(kl % STAGES) * STAGE_BYTES;
        float4 f0, f1;
        if (kl < NITER) {
            if (a_act) {
                const float* ag = agbase + (size_t)kl * KTILE;
                f0 = ((const float4*)ag)[0];
                f1 = ((const float4*)ag)[1];
            }
            uint32_t bb = sb + pslot + 8192;
            int r = bc0 >> 3, c = bc0 & 7;
            cpa16(bb + sw128((uint32_t)(r * 128 + c * 16)),
                  BT + (size_t)r * NN + (size_t)kl * KTILE + c * 8);
            r = bc1 >> 3; c = bc1 & 7;
            cpa16(bb + sw128((uint32_t)(r * 128 + c * 16)),
                  BT + (size_t)r * NN + (size_t)kl * KTILE + c * 8);
        }
        asm volatile("cp.async.commit_group;" ::: "memory");

        uint32_t ab = sb + (uint32_t)(kt % STAGES) * STAGE_BYTES;
        uint32_t bb = ab + 8192;
        if (mma_act) {
#pragma unroll
            for (int s = 0; s < 4; s++) {                    // 4 x k=16 steps
                uint32_t A[4], B[2][4];
                ldsm4(A, ab + sw128(arow + acolsel + (uint32_t)s * 32));
#pragma unroll
                for (int p = 0; p < 2; p++)
                    ldsm4(B[p], bb + sw128(brow[p] + bcolsel + (uint32_t)s * 32));
                mma16(acc[0], A, B[0][0], B[0][1]);
                mma16(acc[1], A, B[0][2], B[0][3]);
                mma16(acc[2], A, B[1][0], B[1][1]);
                mma16(acc[3], A, B[1][2], B[1][3]);
            }
        }

        if (kl < NITER && a_act) {
            *(uint4*)(smem + pslot + ast) =
                make_uint4(pack_h2(f0.x, f0.y), pack_h2(f0.z, f0.w),
                           pack_h2(f1.x, f1.y), pack_h2(f1.z, f1.w));
        }
        asm volatile("cp.async.wait_group %0;" :: "n"(STAGES - 2) : "memory");
        __syncthreads();
    }

    // ---- epilogue phase 1: accum -> elu(+bias) -> Hs smem (pitch 129)
    float* Hs = (float*)smem;            // reuses stage region
    float* bsm = (float*)(smem + SM_BS);
    if (mma_act) {
#pragma unroll
        for (int nf = 0; nf < 4; nf++)
#pragma unroll
            for (int r = 0; r < 4; r++) {
                int row = wm * 16 + (lane >> 2) + ((r >> 1) << 3);
                int col = n_off + nf * 8 + ((lane & 3) << 1) + (r & 1);
                Hs[row * 129 + col] = eluf(acc[nf][r] + bsm[col]);
            }
    }
    __syncthreads();

    // ---- epilogue phase 2
    float* Wsm = (float*)(smem + SM_W);
    if (PASS == 1) {
        // X1T[j][m_start+i] = dot(Hs[i][ho..ho+64), W1 col (j&63)), ho = (j>=64)*64
        int i = tid & 63;
        int jg = tid >> 6;               // 0..7 -> j in [jg*16, jg*16+16)
        if (i < MROWS) {
            int ho = (jg >= 4) ? 64 : 0;
            float h[64];
#pragma unroll
            for (int c = 0; c < 64; c++) h[c] = Hs[i * 129 + ho + c];
#pragma unroll 4
            for (int q = 0; q < 16; q++) {
                int j = jg * 16 + q;
                const float4* wr = (const float4*)(Wsm + (j & 63) * 64);
                float a = 0.f;
#pragma unroll
                for (int t = 0; t < 16; t++) {
                    float4 w = wr[t];
                    a += h[4 * t] * w.x + h[4 * t + 1] * w.y + h[4 * t + 2] * w.z + h[4 * t + 3] * w.w;
                }
                OUTH[(size_t)j * NN + m_start + i] = __float2half_rn(a);
            }
        }
    } else {
        // out[m_start+r][o] = bl[o] + sum_j Hs[r][j] * Wl[o][j]
        int r = tid >> 3;
        int og = (tid & 7) << 2;
        if (r < MROWS) {
            float a[4];
#pragma unroll
            for (int o = 0; o < 4; o++) a[o] = __ldg(bl + og + o);
            for (int j = 0; j < 128; j++) {
                float hv = Hs[r * 129 + j];
                float4 w = *(const float4*)(Wsm + j * 32 + og);
                a[0] += hv * w.x; a[1] += hv * w.y; a[2] += hv * w.z; a[3] += hv * w.w;
            }
            *(float4*)(OUT + (size_t)(m_start + r) * 32 + og) =
                make_float4(a[0], a[1], a[2], a[3]);
        }
    }
}

template <int PASS>
__global__ void __launch_bounds__(512, 1) gemm_kernel(const float* __restrict__ adj,
                                                      const __half* __restrict__ BT,
                                                      const float* __restrict__ bias,
                                                      const float* __restrict__ W2,
                                                      const float* __restrict__ bl,
                                                      float* __restrict__ OUT,
                                                      __half* __restrict__ OUTH,
                                                      int abig) {
    extern __shared__ char smem[];
    uint32_t sb = smem_u32(smem);
    int bid = blockIdx.x;
    if (bid < abig)
        gemm_body<PASS, 64>(adj, BT, bias, W2, bl, OUT, OUTH, bid * 64, smem, sb);
    else
        gemm_body<PASS, 48>(adj, BT, bias, W2, bl, OUT, OUTH,
                            abig * 64 + (bid - abig) * 48, smem, sb);
}

// ---------------------------------------------------------------- launch
extern "C" void kernel_launch(void* const* d_in, const int* in_sizes, int n_in,
                              void* d_out, int out_size) {
    const float* z   = (const float*)d_in[0];
    const float* adj = (const float*)d_in[1];
    const float* W0  = (const float*)d_in[2];
    const float* b0  = (const float*)d_in[3];
    const float* W1  = (const float*)d_in[4];
    const float* b1  = (const float*)d_in[5];
    const float* Wl  = (const float*)d_in[6];
    const float* bl  = (const float*)d_in[7];
    float* out = (float*)d_out;

    __half *x0t = nullptr, *x1t = nullptr;
    cudaGetSymbolAddress((void**)&x0t, g_X0T);
    cudaGetSymbolAddress((void**)&x1t, g_X1T);

    // units: abig x 64 rows + (grid-abig) x 48 rows == 16384, grid = 2*NSM
    int dev = 0, nsm = 148;
    cudaGetDevice(&dev);
    cudaDeviceGetAttribute(&nsm, cudaDevAttrMultiProcessorCount, dev);
    if (nsm < 128) nsm = 128;
    if (nsm > 170) nsm = 170;
    int grid = 2 * nsm;
    int abig = 1024 - 6 * nsm;           // 64*abig + 48*(grid-abig) = 16384

    cudaFuncSetAttribute(prep_kernel, cudaFuncAttributeMaxDynamicSharedMemorySize, PREP_SMEM);
    cudaFuncSetAttribute(gemm_kernel<1>, cudaFuncAttributeMaxDynamicSharedMemorySize, GEMM_SMEM);
    cudaFuncSetAttribute(gemm_kernel<2>, cudaFuncAttributeMaxDynamicSharedMemorySize, GEMM_SMEM);

    prep_kernel<<<NN / 128, 512, PREP_SMEM>>>(z, W0, x0t);
    gemm_kernel<1><<<grid, 512, GEMM_SMEM>>>(adj, x0t, b0, W1, nullptr, nullptr, x1t, abig);
    gemm_kernel<2><<<grid, 512, GEMM_SMEM>>>(adj, x1t, b1, Wl, bl, out, nullptr, abig);
}

// round 14
// speedup vs baseline: 1.1140x; 1.1140x over previous
#include <cuda_runtime.h>
#include <cuda_fp16.h>
#include <cstdint>
#include <math.h>

#define DI __device__ __forceinline__

constexpr int NN = 16384;
constexpr int STAGES = 4;
constexpr int KTILE = 64;
constexpr int NITER = NN / KTILE;                 // 256
constexpr int STAGE_BYTES = 32768;                // A fp16 16K + B fp16 16K
constexpr uint32_t SM_W = STAGES * STAGE_BYTES;   // 131072
constexpr uint32_t SM_BS = SM_W + 16384;          // 147456
constexpr uint32_t GEMM_SMEM = SM_BS + 512;       // 147968
constexpr uint32_t PREP_SMEM = 66048 + 16384;     // Es + W0T

// Inter-layer transposed feature panels (fp16): X?T[j][i] = X[i][j]
__device__ __half g_X0T[128 * NN];
__device__ __half g_X1T[128 * NN];

// ---------------------------------------------------------------- helpers
DI uint32_t smem_u32(const void* p) {
    uint32_t a;
    asm("{ .reg .u64 t; cvta.to.shared.u64 t, %1; cvt.u32.u64 %0, t; }" : "=r"(a) : "l"(p));
    return a;
}
DI uint32_t sw128(uint32_t b) { return b ^ ((b >> 3) & 0x70); }
DI float eluf(float x) { return x > 0.f ? x : expm1f(x); }

DI void cpa16(uint32_t s, const void* g) {
    asm volatile("cp.async.cg.shared.global [%0], [%1], 16;" :: "r"(s), "l"(g));
}
DI void ldsm4(uint32_t* r, uint32_t addr) {
    asm volatile("ldmatrix.sync.aligned.m8n8.x4.shared.b16 {%0,%1,%2,%3}, [%4];"
                 : "=r"(r[0]), "=r"(r[1]), "=r"(r[2]), "=r"(r[3]) : "r"(addr));
}
DI void mma16(float* d, const uint32_t* a, uint32_t b0, uint32_t b1) {
    asm volatile(
        "mma.sync.aligned.m16n8k16.row.col.f32.f16.f16.f32 "
        "{%0,%1,%2,%3}, {%4,%5,%6,%7}, {%8,%9}, {%0,%1,%2,%3};"
        : "+f"(d[0]), "+f"(d[1]), "+f"(d[2]), "+f"(d[3])
        : "r"(a[0]), "r"(a[1]), "r"(a[2]), "r"(a[3]), "r"(b0), "r"(b1));
}
DI uint32_t pack_h2(float lo, float hi) {
    __half2 h = __floats2half2_rn(lo, hi);
    return *reinterpret_cast<uint32_t*>(&h);
}

// ---------------------------------------------------------------- prep: X0T = [elu(zs)@W0 ; elu(zu)@W0]^T  (fp16)
__global__ void __launch_bounds__(512) prep_kernel(const float* __restrict__ z,
                                                   const float* __restrict__ W0,
                                                   __half* __restrict__ X0T) {
    extern __shared__ char smem[];
    float* Es = (float*)smem;            // [128][129] elu(z) rows
    float* Ws = (float*)(smem + 66048);  // [64][64]  W0^T: Ws[j][c] = W0[c][j]
    int tid = threadIdx.x;
    int m0 = blockIdx.x * 128;

    for (int e = tid; e < 128 * 128; e += 512) {
        int i = e >> 7, c = e & 127;
        Es[i * 129 + c] = eluf(z[(size_t)(m0 + i) * 128 + c]);
    }
    for (int e = tid; e < 64 * 64; e += 512) {
        int j = e >> 6, c = e & 63;
        Ws[j * 64 + c] = W0[c * 64 + j];
    }
    __syncthreads();

    int i = tid & 127;
    int part = tid >> 7;          // 0..3
    int ho = (part & 1) * 64;     // s/u half
    int j0 = (part >> 1) * 32;    // feature half
    float h[64];
#pragma unroll
    for (int c = 0; c < 64; c++) h[c] = Es[i * 129 + ho + c];
    for (int jj = j0; jj < j0 + 32; jj++) {
        const float4* wr = (const float4*)(Ws + jj * 64);
        float acc = 0.f;
#pragma unroll
        for (int q = 0; q < 16; q++) {
            float4 w = wr[q];
            acc += h[4 * q] * w.x + h[4 * q + 1] * w.y + h[4 * q + 2] * w.z + h[4 * q + 3] * w.w;
        }
        X0T[(size_t)(ho + jj) * NN + m0 + i] = __float2half_rn(acc);
    }
}

// ---------------------------------------------------------------- GEMM body for one M-unit (MROWS = MFRAGS*16, 112 or 96)
// 16 warps = 8 N-strips (16 cols) x 2 M-parities. Warp (strip, p) computes
// frag rows {p, p+2, ...} of its strip. Parity = (wid>>2)&1 -> every SMSP has
// 2 parity-0 + 2 parity-1 warps: per-SMSP mma load exactly MFRAGS*4 per k-step.
template <int PASS, int MFRAGS>
DI void gemm_body(const float* __restrict__ adj, const __half* __restrict__ BT,
                  const float* __restrict__ bias, const float* __restrict__ W2,
                  const float* __restrict__ bl, float* __restrict__ OUT,
                  __half* __restrict__ OUTH, int m_start, char* smem, uint32_t sb) {
    constexpr int MROWS = MFRAGS * 16;
    int tid = threadIdx.x, wid = tid >> 5, lane = tid & 31;

    // preload epilogue weights + bias (region disjoint from stages)
    {
        float* Wsm = (float*)(smem + SM_W);
        if (PASS == 1) {
            for (int e = tid; e < 64 * 64; e += 512)        // W1^T: Wsm[j*64+c]=W1[c][j]
                Wsm[e] = W2[(e & 63) * 64 + (e >> 6)];
        } else {
            for (int e = tid; e < 128 * 32; e += 512)       // Wl^T: Wsm[j*32+o]=Wl[o][j]
                Wsm[e] = W2[(e & 31) * 128 + (e >> 5)];
        }
        float* bsm = (float*)(smem + SM_BS);
        if (tid < 128) bsm[tid] = bias[tid & 63];
    }

    // A staging (fp32->fp16): 4 threads/row, 16 floats each; rows < MROWS
    int arid = tid >> 2;                 // 0..127
    int aseg = tid & 3;
    bool a_act = arid < MROWS;
    const float* agbase = adj + (size_t)(m_start + arid) * NN + aseg * 16;
    uint32_t ast0 = sw128((uint32_t)(arid * 128 + aseg * 32));
    uint32_t ast1 = sw128((uint32_t)(arid * 128 + aseg * 32 + 16));

    // B staging: 2 x 16B chunks per thread (1024 chunks: r=chunk>>3, c=chunk&7)
    int bc0 = tid, bc1 = tid + 512;

    // warp -> (strip, parity): p=(wid>>2)&1; strip=(wid&3)|((wid>>3)<<2)
    int p = (wid >> 2) & 1;
    int strip = (wid & 3) | ((wid >> 3) << 2);
    int n_off = strip * 16;
    int r8 = lane & 7;
    // A frag lane base (byte offset, add mf*2048 + s*32, swizzle at use)
    uint32_t abase = (uint32_t)((r8 + ((lane >> 3) & 1) * 8) * 128 + ((lane >> 4) & 1) * 16);
    // B frag base: 16 n-rows x 16 k per k-step (ldsm x4)
    uint32_t bbase = (uint32_t)((n_off + r8 + ((lane >> 4) & 1) * 8) * 128 + ((lane >> 3) & 1) * 16);

    constexpr int NMF = (MFRAGS + 1) / 2;    // frags this warp handles at most
    float acc[NMF][2][4];
#pragma unroll
    for (int t = 0; t < NMF; t++)
#pragma unroll
        for (int nf = 0; nf < 2; nf++)
#pragma unroll
            for (int r = 0; r < 4; r++) acc[t][nf][r] = 0.f;

    // ---- prologue: stage tiles 0..STAGES-2
#pragma unroll
    for (int pp = 0; pp < STAGES - 1; pp++) {
        uint32_t abo = (uint32_t)pp * STAGE_BYTES;
        if (a_act) {
            const float* ag = agbase + (size_t)pp * KTILE;
            float4 f0 = ((const float4*)ag)[0], f1 = ((const float4*)ag)[1];
            float4 f2 = ((const float4*)ag)[2], f3 = ((const float4*)ag)[3];
            *(uint4*)(smem + abo + ast0) =
                make_uint4(pack_h2(f0.x, f0.y), pack_h2(f0.z, f0.w),
                           pack_h2(f1.x, f1.y), pack_h2(f1.z, f1.w));
            *(uint4*)(smem + abo + ast1) =
                make_uint4(pack_h2(f2.x, f2.y), pack_h2(f2.z, f2.w),
                           pack_h2(f3.x, f3.y), pack_h2(f3.z, f3.w));
        }
        uint32_t bb = sb + abo + 16384;
        int r = bc0 >> 3, c = bc0 & 7;
        cpa16(bb + sw128((uint32_t)(r * 128 + c * 16)),
              BT + (size_t)r * NN + (size_t)pp * KTILE + c * 8);
        r = bc1 >> 3; c = bc1 & 7;
        cpa16(bb + sw128((uint32_t)(r * 128 + c * 16)),
              BT + (size_t)r * NN + (size_t)pp * KTILE + c * 8);
        asm volatile("cp.async.commit_group;" ::: "memory");
    }
    asm volatile("cp.async.wait_group %0;" :: "n"(STAGES - 2) : "memory");
    __syncthreads();

    // ---- mainloop
    for (int kt = 0; kt < NITER; kt++) {
        int kl = kt + STAGES - 1;
        uint32_t pslot = (uint32_t)(kl % STAGES) * STAGE_BYTES;
        float4 f0, f1, f2, f3;
        if (kl < NITER) {
            if (a_act) {
                const float* ag = agbase + (size_t)kl * KTILE;
                f0 = ((const float4*)ag)[0]; f1 = ((const float4*)ag)[1];
                f2 = ((const float4*)ag)[2]; f3 = ((const float4*)ag)[3];
            }
            uint32_t bb = sb + pslot + 16384;
            int r = bc0 >> 3, c = bc0 & 7;
            cpa16(bb + sw128((uint32_t)(r * 128 + c * 16)),
                  BT + (size_t)r * NN + (size_t)kl * KTILE + c * 8);
            r = bc1 >> 3; c = bc1 & 7;
            cpa16(bb + sw128((uint32_t)(r * 128 + c * 16)),
                  BT + (size_t)r * NN + (size_t)kl * KTILE + c * 8);
        }
        asm volatile("cp.async.commit_group;" ::: "memory");

        uint32_t ab = sb + (uint32_t)(kt % STAGES) * STAGE_BYTES;
        uint32_t bb = ab + 16384;
#pragma unroll
        for (int s = 0; s < 4; s++) {                        // 4 x k=16 steps
            uint32_t B[4];
            ldsm4(B, bb + sw128(bbase + (uint32_t)s * 32));
#pragma unroll
            for (int t = 0; t < NMF; t++) {
                int mf = p + 2 * t;
                if (mf < MFRAGS) {
                    uint32_t A[4];
                    ldsm4(A, ab + sw128(abase + (uint32_t)mf * 2048 + (uint32_t)s * 32));
                    mma16(acc[t][0], A, B[0], B[1]);
                    mma16(acc[t][1], A, B[2], B[3]);
                }
            }
        }

        if (kl < NITER && a_act) {
            *(uint4*)(smem + pslot + ast0) =
                make_uint4(pack_h2(f0.x, f0.y), pack_h2(f0.z, f0.w),
                           pack_h2(f1.x, f1.y), pack_h2(f1.z, f1.w));
            *(uint4*)(smem + pslot + ast1) =
                make_uint4(pack_h2(f2.x, f2.y), pack_h2(f2.z, f2.w),
                           pack_h2(f3.x, f3.y), pack_h2(f3.z, f3.w));
        }
        asm volatile("cp.async.wait_group %0;" :: "n"(STAGES - 2) : "memory");
        __syncthreads();
    }

    // ---- epilogue phase 1: accum -> elu(+bias) -> Hs smem (pitch 129)
    float* Hs = (float*)smem;            // reuses stage region
    float* bsm = (float*)(smem + SM_BS);
#pragma unroll
    for (int t = 0; t < NMF; t++) {
        int mf = p + 2 * t;
        if (mf < MFRAGS) {
#pragma unroll
            for (int nf = 0; nf < 2; nf++)
#pragma unroll
                for (int r = 0; r < 4; r++) {
                    int row = mf * 16 + (lane >> 2) + ((r >> 1) << 3);
                    int col = n_off + nf * 8 + ((lane & 3) << 1) + (r & 1);
                    Hs[row * 129 + col] = eluf(acc[t][nf][r] + bsm[col]);
                }
        }
    }
    __syncthreads();

    // ---- epilogue phase 2
    float* Wsm = (float*)(smem + SM_W);
    if (PASS == 1) {
        // X1T[ho+jj][m_start+i] = dot(Hs[i][ho..ho+64), W1 col jj)
        int i = tid & 127;
        int part = tid >> 7;
        if (i < MROWS) {
            int ho = (part & 1) * 64;
            int j0 = (part >> 1) * 32;
            float h[64];
#pragma unroll
            for (int c = 0; c < 64; c++) h[c] = Hs[i * 129 + ho + c];
            for (int jj = j0; jj < j0 + 32; jj++) {
                const float4* wr = (const float4*)(Wsm + jj * 64);
                float a = 0.f;
#pragma unroll
                for (int q = 0; q < 16; q++) {
                    float4 w = wr[q];
                    a += h[4 * q] * w.x + h[4 * q + 1] * w.y + h[4 * q + 2] * w.z + h[4 * q + 3] * w.w;
                }
                OUTH[(size_t)(ho + jj) * NN + m_start + i] = __float2half_rn(a);
            }
        }
    } else {
        // out[m_start+r][o] = bl[o] + sum_j Hs[r][j] * Wl[o][j]
        int r = tid >> 2;
        int og = (tid & 3) << 3;
        if (r < MROWS) {
            float a[8];
#pragma unroll
            for (int o = 0; o < 8; o++) a[o] = __ldg(bl + og + o);
            for (int j = 0; j < 128; j++) {
                float hv = Hs[r * 129 + j];
                const float4* wr = (const float4*)(Wsm + j * 32 + og);
#pragma unroll
                for (int q = 0; q < 2; q++) {
                    float4 w = wr[q];
                    a[4 * q + 0] += hv * w.x;
                    a[4 * q + 1] += hv * w.y;
                    a[4 * q + 2] += hv * w.z;
                    a[4 * q + 3] += hv * w.w;
                }
            }
            float4* op = (float4*)(OUT + (size_t)(m_start + r) * 32 + og);
#pragma unroll
            for (int q = 0; q < 2; q++)
                op[q] = make_float4(a[4 * q], a[4 * q + 1], a[4 * q + 2], a[4 * q + 3]);
        }
    }
}

template <int PASS>
__global__ void __launch_bounds__(512, 1) gemm_kernel(const float* __restrict__ adj,
                                                      const __half* __restrict__ BT,
                                                      const float* __restrict__ bias,
                                                      const float* __restrict__ W2,
                                                      const float* __restrict__ bl,
                                                      float* __restrict__ OUT,
                                                      __half* __restrict__ OUTH,
                                                      int abig) {
    extern __shared__ char smem[];
    uint32_t sb = smem_u32(smem);
    int bid = blockIdx.x;
    if (bid < abig)
        gemm_body<PASS, 7>(adj, BT, bias, W2, bl, OUT, OUTH, bid * 112, smem, sb);
    else
        gemm_body<PASS, 6>(adj, BT, bias, W2, bl, OUT, OUTH,
                           abig * 112 + (bid - abig) * 96, smem, sb);
}

// ---------------------------------------------------------------- launch
extern "C" void kernel_launch(void* const* d_in, const int* in_sizes, int n_in,
                              void* d_out, int out_size) {
    const float* z   = (const float*)d_in[0];
    const float* adj = (const float*)d_in[1];
    const float* W0  = (const float*)d_in[2];
    const float* b0  = (const float*)d_in[3];
    const float* W1  = (const float*)d_in[4];
    const float* b1  = (const float*)d_in[5];
    const float* Wl  = (const float*)d_in[6];
    const float* bl  = (const float*)d_in[7];
    float* out = (float*)d_out;

    __half *x0t = nullptr, *x1t = nullptr;
    cudaGetSymbolAddress((void**)&x0t, g_X0T);
    cudaGetSymbolAddress((void**)&x1t, g_X1T);

    // one CTA per SM, single wave: abig x 112 rows + (g-abig) x 96 rows == 16384
    int dev = 0, nsm = 148;
    cudaGetDevice(&dev);
    cudaDeviceGetAttribute(&nsm, cudaDevAttrMultiProcessorCount, dev);
    if (nsm < 147) nsm = 147;
    if (nsm > 170) nsm = 170;
    int grid = nsm;
    int abig = 1024 - 6 * nsm;           // 112*abig + 96*(grid-abig) = 16384

    cudaFuncSetAttribute(prep_kernel, cudaFuncAttributeMaxDynamicSharedMemorySize, PREP_SMEM);
    cudaFuncSetAttribute(gemm_kernel<1>, cudaFuncAttributeMaxDynamicSharedMemorySize, GEMM_SMEM);
    cudaFuncSetAttribute(gemm_kernel<2>, cudaFuncAttributeMaxDynamicSharedMemorySize, GEMM_SMEM);

    prep_kernel<<<NN / 128, 512, PREP_SMEM>>>(z, W0, x0t);
    gemm_kernel<1><<<grid, 512, GEMM_SMEM>>>(adj, x0t, b0, W1, nullptr, nullptr, x1t, abig);
    gemm_kernel<2><<<grid, 512, GEMM_SMEM>>>(adj, x1t, b1, Wl, bl, out, nullptr, abig);
}

// round 15
// speedup vs baseline: 1.1695x; 1.0498x over previous
#include <cuda_runtime.h>
#include <cuda_fp16.h>
#include <cstdint>
#include <math.h>

#define DI __device__ __forceinline__

constexpr int NN = 16384;
constexpr int STAGES = 4;
constexpr int KTILE = 64;
constexpr int NITER = NN / KTILE;                 // 256
constexpr int STAGE_BYTES = 32768;                // A fp16 16K + B fp16 16K
constexpr uint32_t SM_W = STAGES * STAGE_BYTES;   // 131072
constexpr uint32_t SM_BS = SM_W + 16384;          // 147456
constexpr uint32_t GEMM_SMEM = SM_BS + 512;       // 147968
constexpr uint32_t PREP_SMEM = 66048 + 16384;     // Es + W0T

// Inter-layer transposed feature panels (fp16): X?T[j][i] = X[i][j]
__device__ __half g_X0T[128 * NN];
__device__ __half g_X1T[128 * NN];

// ---------------------------------------------------------------- helpers
DI uint32_t smem_u32(const void* p) {
    uint32_t a;
    asm("{ .reg .u64 t; cvta.to.shared.u64 t, %1; cvt.u32.u64 %0, t; }" : "=r"(a) : "l"(p));
    return a;
}
DI uint32_t sw128(uint32_t b) { return b ^ ((b >> 3) & 0x70); }
DI float eluf(float x) { return x > 0.f ? x : expm1f(x); }

DI void cpa16(uint32_t s, const void* g) {
    asm volatile("cp.async.cg.shared.global [%0], [%1], 16;" :: "r"(s), "l"(g));
}
DI void ldsm4(uint32_t* r, uint32_t addr) {
    asm volatile("ldmatrix.sync.aligned.m8n8.x4.shared.b16 {%0,%1,%2,%3}, [%4];"
                 : "=r"(r[0]), "=r"(r[1]), "=r"(r[2]), "=r"(r[3]) : "r"(addr));
}
DI void mma16(float* d, const uint32_t* a, uint32_t b0, uint32_t b1) {
    asm volatile(
        "mma.sync.aligned.m16n8k16.row.col.f32.f16.f16.f32 "
        "{%0,%1,%2,%3}, {%4,%5,%6,%7}, {%8,%9}, {%0,%1,%2,%3};"
        : "+f"(d[0]), "+f"(d[1]), "+f"(d[2]), "+f"(d[3])
        : "r"(a[0]), "r"(a[1]), "r"(a[2]), "r"(a[3]), "r"(b0), "r"(b1));
}
DI uint32_t pack_h2(float lo, float hi) {
    __half2 h = __floats2half2_rn(lo, hi);
    return *reinterpret_cast<uint32_t*>(&h);
}

// ---------------------------------------------------------------- prep: X0T = [elu(zs)@W0 ; elu(zu)@W0]^T  (fp16)
__global__ void __launch_bounds__(512) prep_kernel(const float* __restrict__ z,
                                                   const float* __restrict__ W0,
                                                   __half* __restrict__ X0T) {
    extern __shared__ char smem[];
    float* Es = (float*)smem;            // [128][129] elu(z) rows
    float* Ws = (float*)(smem + 66048);  // [64][64]  W0^T: Ws[j][c] = W0[c][j]
    int tid = threadIdx.x;
    int m0 = blockIdx.x * 128;

    for (int e = tid; e < 128 * 128; e += 512) {
        int i = e >> 7, c = e & 127;
        Es[i * 129 + c] = eluf(z[(size_t)(m0 + i) * 128 + c]);
    }
    for (int e = tid; e < 64 * 64; e += 512) {
        int j = e >> 6, c = e & 63;
        Ws[j * 64 + c] = W0[c * 64 + j];
    }
    __syncthreads();

    int i = tid & 127;
    int part = tid >> 7;          // 0..3
    int ho = (part & 1) * 64;     // s/u half
    int j0 = (part >> 1) * 32;    // feature half
    float h[64];
#pragma unroll
    for (int c = 0; c < 64; c++) h[c] = Es[i * 129 + ho + c];
    for (int jj = j0; jj < j0 + 32; jj++) {
        const float4* wr = (const float4*)(Ws + jj * 64);
        float acc = 0.f;
#pragma unroll
        for (int q = 0; q < 16; q++) {
            float4 w = wr[q];
            acc += h[4 * q] * w.x + h[4 * q + 1] * w.y + h[4 * q + 2] * w.z + h[4 * q + 3] * w.w;
        }
        X0T[(size_t)(ho + jj) * NN + m0 + i] = __float2half_rn(acc);
    }
}

// ---------------------------------------------------------------- GEMM body for one M-unit (MROWS = MFRAGS*16, 112 or 96)
// R10 structure; warp map SWAPPED so M-groups spread across SMSPs:
//   m_off = (wid>>2)*32 (M group), n_off = (wid&3)*32 (N strip = SMSP id).
// Each SMSP holds one warp of each M-group -> trimming the last M frag removes
// exactly 1/8 of mma work from EVERY SMSP (28/32 for M=112), stays balanced.
template <int PASS, int MFRAGS>
DI void gemm_body(const float* __restrict__ adj, const __half* __restrict__ BT,
                  const float* __restrict__ bias, const float* __restrict__ W2,
                  const float* __restrict__ bl, float* __restrict__ OUT,
                  __half* __restrict__ OUTH, int m_start, char* smem, uint32_t sb) {
    constexpr int MROWS = MFRAGS * 16;
    int tid = threadIdx.x, wid = tid >> 5, lane = tid & 31;

    // preload epilogue weights + bias (region disjoint from stages)
    {
        float* Wsm = (float*)(smem + SM_W);
        if (PASS == 1) {
            for (int e = tid; e < 64 * 64; e += 512)        // W1^T: Wsm[j*64+c]=W1[c][j]
                Wsm[e] = W2[(e & 63) * 64 + (e >> 6)];
        } else {
            for (int e = tid; e < 128 * 32; e += 512)       // Wl^T: Wsm[j*32+o]=Wl[o][j]
                Wsm[e] = W2[(e & 31) * 128 + (e >> 5)];
        }
        float* bsm = (float*)(smem + SM_BS);
        if (tid < 128) bsm[tid] = bias[tid & 63];
    }

    // A staging (fp32->fp16): 4 threads/row, 16 floats each; only rows < MROWS
    int arid = tid >> 2;                 // 0..127
    int aseg = tid & 3;
    bool a_act = arid < MROWS;
    const float* agbase = adj + (size_t)(m_start + arid) * NN + aseg * 16;
    uint32_t ast0 = sw128((uint32_t)(arid * 128 + aseg * 32));
    uint32_t ast1 = sw128((uint32_t)(arid * 128 + aseg * 32 + 16));

    // B staging: 2 x 16B chunks per thread (1024 chunks: r=chunk>>3, c=chunk&7)
    int bc0 = tid, bc1 = tid + 512;

    // warp fragment bases (m/n SWAPPED vs R10)
    int m_off = (wid >> 2) * 32;
    int n_off = (wid & 3) * 32;
    int r8 = lane & 7;
    uint32_t arow[2];
#pragma unroll
    for (int mf = 0; mf < 2; mf++)
        arow[mf] = (uint32_t)((m_off + mf * 16 + r8 + ((lane >> 3) & 1) * 8) * 128);
    uint32_t acolsel = (uint32_t)(((lane >> 4) & 1) * 16);
    uint32_t brow[2];
#pragma unroll
    for (int p = 0; p < 2; p++)
        brow[p] = (uint32_t)((n_off + p * 16 + r8 + ((lane >> 4) & 1) * 8) * 128);
    uint32_t bcolsel = (uint32_t)(((lane >> 3) & 1) * 16);

    // which of this warp's 2 M-frags are active (compile-time per MFRAGS, uniform per warp)
    bool act0 = (m_off >> 4) + 0 < MFRAGS;
    bool act1 = (m_off >> 4) + 1 < MFRAGS;

    float acc[2][4][4];
#pragma unroll
    for (int mf = 0; mf < 2; mf++)
#pragma unroll
        for (int nf = 0; nf < 4; nf++)
#pragma unroll
            for (int r = 0; r < 4; r++) acc[mf][nf][r] = 0.f;

    // ---- prologue: fully stage tiles 0..STAGES-2
#pragma unroll
    for (int p = 0; p < STAGES - 1; p++) {
        uint32_t abo = (uint32_t)p * STAGE_BYTES;
        if (a_act) {
            const float* ag = agbase + (size_t)p * KTILE;
            float4 f0 = ((const float4*)ag)[0], f1 = ((const float4*)ag)[1];
            float4 f2 = ((const float4*)ag)[2], f3 = ((const float4*)ag)[3];
            *(uint4*)(smem + abo + ast0) =
                make_uint4(pack_h2(f0.x, f0.y), pack_h2(f0.z, f0.w),
                           pack_h2(f1.x, f1.y), pack_h2(f1.z, f1.w));
            *(uint4*)(smem + abo + ast1) =
                make_uint4(pack_h2(f2.x, f2.y), pack_h2(f2.z, f2.w),
                           pack_h2(f3.x, f3.y), pack_h2(f3.z, f3.w));
        }
        uint32_t bb = sb + abo + 16384;
        int r = bc0 >> 3, c = bc0 & 7;
        cpa16(bb + sw128((uint32_t)(r * 128 + c * 16)),
              BT + (size_t)r * NN + (size_t)p * KTILE + c * 8);
        r = bc1 >> 3; c = bc1 & 7;
        cpa16(bb + sw128((uint32_t)(r * 128 + c * 16)),
              BT + (size_t)r * NN + (size_t)p * KTILE + c * 8);
        asm volatile("cp.async.commit_group;" ::: "memory");
    }
    asm volatile("cp.async.wait_group %0;" :: "n"(STAGES - 2) : "memory");
    __syncthreads();   // stage 0 ready (covers A STS + Wsm/bsm)

    // ---- mainloop
    for (int kt = 0; kt < NITER; kt++) {
        int kl = kt + STAGES - 1;
        uint32_t pslot = (uint32_t)(kl % STAGES) * STAGE_BYTES;
        float4 f0, f1, f2, f3;
        if (kl < NITER) {
            if (a_act) {
                const float* ag = agbase + (size_t)kl * KTILE;
                f0 = ((const float4*)ag)[0]; f1 = ((const float4*)ag)[1];
                f2 = ((const float4*)ag)[2]; f3 = ((const float4*)ag)[3];
            }
            uint32_t bb = sb + pslot + 16384;
            int r = bc0 >> 3, c = bc0 & 7;
            cpa16(bb + sw128((uint32_t)(r * 128 + c * 16)),
                  BT + (size_t)r * NN + (size_t)kl * KTILE + c * 8);
            r = bc1 >> 3; c = bc1 & 7;
            cpa16(bb + sw128((uint32_t)(r * 128 + c * 16)),
                  BT + (size_t)r * NN + (size_t)kl * KTILE + c * 8);
        }
        asm volatile("cp.async.commit_group;" ::: "memory");

        uint32_t ab = sb + (uint32_t)(kt % STAGES) * STAGE_BYTES;
        uint32_t bb = ab + 16384;
#pragma unroll
        for (int s = 0; s < 4; s++) {                        // 4 x k=16 steps
            uint32_t A[2][4], B[2][4];
            if (act0) ldsm4(A[0], ab + sw128(arow[0] + acolsel + (uint32_t)s * 32));
            if (act1) ldsm4(A[1], ab + sw128(arow[1] + acolsel + (uint32_t)s * 32));
#pragma unroll
            for (int p = 0; p < 2; p++)
                ldsm4(B[p], bb + sw128(brow[p] + bcolsel + (uint32_t)s * 32));
            if (act0) {
                mma16(acc[0][0], A[0], B[0][0], B[0][1]);
                mma16(acc[0][1], A[0], B[0][2], B[0][3]);
                mma16(acc[0][2], A[0], B[1][0], B[1][1]);
                mma16(acc[0][3], A[0], B[1][2], B[1][3]);
            }
            if (act1) {
                mma16(acc[1][0], A[1], B[0][0], B[0][1]);
                mma16(acc[1][1], A[1], B[0][2], B[0][3]);
                mma16(acc[1][2], A[1], B[1][0], B[1][1]);
                mma16(acc[1][3], A[1], B[1][2], B[1][3]);
            }
        }

        if (kl < NITER && a_act) {   // stage prefetched A tile
            *(uint4*)(smem + pslot + ast0) =
                make_uint4(pack_h2(f0.x, f0.y), pack_h2(f0.z, f0.w),
                           pack_h2(f1.x, f1.y), pack_h2(f1.z, f1.w));
            *(uint4*)(smem + pslot + ast1) =
                make_uint4(pack_h2(f2.x, f2.y), pack_h2(f2.z, f2.w),
                           pack_h2(f3.x, f3.y), pack_h2(f3.z, f3.w));
        }
        asm volatile("cp.async.wait_group %0;" :: "n"(STAGES - 2) : "memory");
        __syncthreads();
    }

    // ---- epilogue phase 1: accum -> elu(+bias) -> Hs smem (pitch 129)
    float* Hs = (float*)smem;            // reuses stage region
    float* bsm = (float*)(smem + SM_BS);
#pragma unroll
    for (int mf = 0; mf < 2; mf++) {
        if ((m_off >> 4) + mf < MFRAGS) {
#pragma unroll
            for (int nf = 0; nf < 4; nf++)
#pragma unroll
                for (int r = 0; r < 4; r++) {
                    int row = m_off + mf * 16 + (lane >> 2) + ((r >> 1) << 3);
                    int col = n_off + nf * 8 + ((lane & 3) << 1) + (r & 1);
                    Hs[row * 129 + col] = eluf(acc[mf][nf][r] + bsm[col]);
                }
        }
    }
    __syncthreads();

    // ---- epilogue phase 2
    float* Wsm = (float*)(smem + SM_W);
    if (PASS == 1) {
        // X1T[ho+jj][m_start+i] = dot(Hs[i][ho..ho+64), W1 col jj)
        int i = tid & 127;
        int part = tid >> 7;
        if (i < MROWS) {
            int ho = (part & 1) * 64;
            int j0 = (part >> 1) * 32;
            float h[64];
#pragma unroll
            for (int c = 0; c < 64; c++) h[c] = Hs[i * 129 + ho + c];
            for (int jj = j0; jj < j0 + 32; jj++) {
                const float4* wr = (const float4*)(Wsm + jj * 64);
                float a = 0.f;
#pragma unroll
                for (int q = 0; q < 16; q++) {
                    float4 w = wr[q];
                    a += h[4 * q] * w.x + h[4 * q + 1] * w.y + h[4 * q + 2] * w.z + h[4 * q + 3] * w.w;
                }
                OUTH[(size_t)(ho + jj) * NN + m_start + i] = __float2half_rn(a);
            }
        }
    } else {
        // out[m_start+r][o] = bl[o] + sum_j Hs[r][j] * Wl[o][j]
        int r = tid >> 2;
        int og = (tid & 3) << 3;
        if (r < MROWS) {
            float a[8];
#pragma unroll
            for (int o = 0; o < 8; o++) a[o] = __ldg(bl + og + o);
            for (int j = 0; j < 128; j++) {
                float hv = Hs[r * 129 + j];
                const float4* wr = (const float4*)(Wsm + j * 32 + og);
#pragma unroll
                for (int q = 0; q < 2; q++) {
                    float4 w = wr[q];
                    a[4 * q + 0] += hv * w.x;
                    a[4 * q + 1] += hv * w.y;
                    a[4 * q + 2] += hv * w.z;
                    a[4 * q + 3] += hv * w.w;
                }
            }
            float4* op = (float4*)(OUT + (size_t)(m_start + r) * 32 + og);
#pragma unroll
            for (int q = 0; q < 2; q++)
                op[q] = make_float4(a[4 * q], a[4 * q + 1], a[4 * q + 2], a[4 * q + 3]);
        }
    }
}

template <int PASS>
__global__ void __launch_bounds__(512, 1) gemm_kernel(const float* __restrict__ adj,
                                                      const __half* __restrict__ BT,
                                                      const float* __restrict__ bias,
                                                      const float* __restrict__ W2,
                                                      const float* __restrict__ bl,
                                                      float* __restrict__ OUT,
                                                      __half* __restrict__ OUTH,
                                                      int abig) {
    extern __shared__ char smem[];
    uint32_t sb = smem_u32(smem);
    int bid = blockIdx.x;
    if (bid < abig)
        gemm_body<PASS, 7>(adj, BT, bias, W2, bl, OUT, OUTH, bid * 112, smem, sb);
    else
        gemm_body<PASS, 6>(adj, BT, bias, W2, bl, OUT, OUTH,
                           abig * 112 + (bid - abig) * 96, smem, sb);
}

// ---------------------------------------------------------------- launch
extern "C" void kernel_launch(void* const* d_in, const int* in_sizes, int n_in,
                              void* d_out, int out_size) {
    const float* z   = (const float*)d_in[0];
    const float* adj = (const float*)d_in[1];
    const float* W0  = (const float*)d_in[2];
    const float* b0  = (const float*)d_in[3];
    const float* W1  = (const float*)d_in[4];
    const float* b1  = (const float*)d_in[5];
    const float* Wl  = (const float*)d_in[6];
    const float* bl  = (const float*)d_in[7];
    float* out = (float*)d_out;

    __half *x0t = nullptr, *x1t = nullptr;
    cudaGetSymbolAddress((void**)&x0t, g_X0T);
    cudaGetSymbolAddress((void**)&x1t, g_X1T);

    // one CTA per SM, single wave: abig x 112 rows + (grid-abig) x 96 rows == 16384
    int dev = 0, nsm = 148;
    cudaGetDevice(&dev);
    cudaDeviceGetAttribute(&nsm, cudaDevAttrMultiProcessorCount, dev);
    if (nsm < 147) nsm = 147;
    if (nsm > 170) nsm = 170;
    int grid = nsm;
    int abig = 1024 - 6 * nsm;           // 112*abig + 96*(grid-abig) = 16384

    cudaFuncSetAttribute(prep_kernel, cudaFuncAttributeMaxDynamicSharedMemorySize, PREP_SMEM);
    cudaFuncSetAttribute(gemm_kernel<1>, cudaFuncAttributeMaxDynamicSharedMemorySize, GEMM_SMEM);
    cudaFuncSetAttribute(gemm_kernel<2>, cudaFuncAttributeMaxDynamicSharedMemorySize, GEMM_SMEM);

    prep_kernel<<<NN / 128, 512, PREP_SMEM>>>(z, W0, x0t);
    gemm_kernel<1><<<grid, 512, GEMM_SMEM>>>(adj, x0t, b0, W1, nullptr, nullptr, x1t, abig);
    gemm_kernel<2><<<grid, 512, GEMM_SMEM>>>(adj, x1t, b1, Wl, bl, out, nullptr, abig);
}

// round 17
// speedup vs baseline: 1.2136x; 1.0377x over previous
#include <cuda_runtime.h>
#include <cuda_fp16.h>
#include <cstdint>
#include <math.h>

#define DI __device__ __forceinline__

constexpr int NN = 16384;
constexpr int STAGES = 4;
constexpr int KTILE = 64;
constexpr int NITER = NN / KTILE;                 // 256
constexpr int STAGE_BYTES = 32768;                // A fp16 16K + B fp16 16K
constexpr uint32_t SM_W = STAGES * STAGE_BYTES;   // 131072
constexpr uint32_t SM_BS = SM_W + 16384;          // 147456
constexpr uint32_t GEMM_SMEM = SM_BS + 512;       // 147968
constexpr uint32_t PREP_SMEM = 66048 + 16384;     // Es + W0T

// Inter-layer transposed feature panels (fp16): X?T[j][i] = X[i][j]
__device__ __half g_X0T[128 * NN];
__device__ __half g_X1T[128 * NN];

// ---------------------------------------------------------------- helpers
DI uint32_t smem_u32(const void* p) {
    uint32_t a;
    asm("{ .reg .u64 t; cvta.to.shared.u64 t, %1; cvt.u32.u64 %0, t; }" : "=r"(a) : "l"(p));
    return a;
}
DI uint32_t sw128(uint32_t b) { return b ^ ((b >> 3) & 0x70); }
DI float eluf(float x) { return x > 0.f ? x : expm1f(x); }

DI void cpa16(uint32_t s, const void* g) {
    asm volatile("cp.async.cg.shared.global [%0], [%1], 16;" :: "r"(s), "l"(g));
}
DI void ldsm4(uint32_t* r, uint32_t addr) {
    asm volatile("ldmatrix.sync.aligned.m8n8.x4.shared.b16 {%0,%1,%2,%3}, [%4];"
                 : "=r"(r[0]), "=r"(r[1]), "=r"(r[2]), "=r"(r[3]) : "r"(addr));
}
DI void mma16(float* d, const uint32_t* a, uint32_t b0, uint32_t b1) {
    asm volatile(
        "mma.sync.aligned.m16n8k16.row.col.f32.f16.f16.f32 "
        "{%0,%1,%2,%3}, {%4,%5,%6,%7}, {%8,%9}, {%0,%1,%2,%3};"
        : "+f"(d[0]), "+f"(d[1]), "+f"(d[2]), "+f"(d[3])
        : "r"(a[0]), "r"(a[1]), "r"(a[2]), "r"(a[3]), "r"(b0), "r"(b1));
}
DI uint32_t pack_h2(float lo, float hi) {
    __half2 h = __floats2half2_rn(lo, hi);
    return *reinterpret_cast<uint32_t*>(&h);
}

// ---------------------------------------------------------------- prep: X0T = [elu(zs)@W0 ; elu(zu)@W0]^T  (fp16)
__global__ void __launch_bounds__(512) prep_kernel(const float* __restrict__ z,
                                                   const float* __restrict__ W0,
                                                   __half* __restrict__ X0T) {
    extern __shared__ char smem[];
    float* Es = (float*)smem;            // [128][129] elu(z) rows
    float* Ws = (float*)(smem + 66048);  // [64][64]  W0^T: Ws[j][c] = W0[c][j]
    int tid = threadIdx.x;
    int m0 = blockIdx.x * 128;

    for (int e = tid; e < 128 * 128; e += 512) {
        int i = e >> 7, c = e & 127;
        Es[i * 129 + c] = eluf(z[(size_t)(m0 + i) * 128 + c]);
    }
    for (int e = tid; e < 64 * 64; e += 512) {
        int j = e >> 6, c = e & 63;
        Ws[j * 64 + c] = W0[c * 64 + j];
    }
    __syncthreads();

    int i = tid & 127;
    int part = tid >> 7;          // 0..3
    int ho = (part & 1) * 64;     // s/u half
    int j0 = (part >> 1) * 32;    // feature half
    float h[64];
#pragma unroll
    for (int c = 0; c < 64; c++) h[c] = Es[i * 129 + ho + c];
    for (int jj = j0; jj < j0 + 32; jj++) {
        const float4* wr = (const float4*)(Ws + jj * 64);
        float acc = 0.f;
#pragma unroll
        for (int q = 0; q < 16; q++) {
            float4 w = wr[q];
            acc += h[4 * q] * w.x + h[4 * q + 1] * w.y + h[4 * q + 2] * w.z + h[4 * q + 3] * w.w;
        }
        X0T[(size_t)(ho + jj) * NN + m0 + i] = __float2half_rn(acc);
    }
}

// ---------------------------------------------------------------- branch-free mainloop, NF m-frags (compile time)
template <int NF>
DI void mainloop_run(const float* agbase, const __half* __restrict__ BT,
                     char* smem, uint32_t sb, bool a_act, int bc0, int bc1,
                     uint32_t ast0, uint32_t ast1,
                     const uint32_t* arow, uint32_t acolsel,
                     const uint32_t* brow, uint32_t bcolsel,
                     float (*acc)[4][4]) {
    constexpr int NFA = NF > 0 ? NF : 1;     // avoid zero-sized array in NF=0 instantiation
    for (int kt = 0; kt < NITER; kt++) {
        int kl = kt + STAGES - 1;
        uint32_t pslot = (uint32_t)(kl % STAGES) * STAGE_BYTES;
        float4 f0, f1, f2, f3;
        if (kl < NITER) {
            if (a_act) {
                const float* ag = agbase + (size_t)kl * KTILE;
                f0 = ((const float4*)ag)[0]; f1 = ((const float4*)ag)[1];
                f2 = ((const float4*)ag)[2]; f3 = ((const float4*)ag)[3];
            }
            uint32_t bb = sb + pslot + 16384;
            int r = bc0 >> 3, c = bc0 & 7;
            cpa16(bb + sw128((uint32_t)(r * 128 + c * 16)),
                  BT + (size_t)r * NN + (size_t)kl * KTILE + c * 8);
            r = bc1 >> 3; c = bc1 & 7;
            cpa16(bb + sw128((uint32_t)(r * 128 + c * 16)),
                  BT + (size_t)r * NN + (size_t)kl * KTILE + c * 8);
        }
        asm volatile("cp.async.commit_group;" ::: "memory");

        uint32_t ab = sb + (uint32_t)(kt % STAGES) * STAGE_BYTES;
        uint32_t bb = ab + 16384;
        if (NF > 0) {
#pragma unroll
            for (int s = 0; s < 4; s++) {                    // 4 x k=16 steps
                uint32_t A[NFA][4], B[2][4];
#pragma unroll
                for (int mf = 0; mf < NF; mf++)
                    ldsm4(A[mf], ab + sw128(arow[mf] + acolsel + (uint32_t)s * 32));
#pragma unroll
                for (int p = 0; p < 2; p++)
                    ldsm4(B[p], bb + sw128(brow[p] + bcolsel + (uint32_t)s * 32));
#pragma unroll
                for (int mf = 0; mf < NF; mf++) {
                    mma16(acc[mf][0], A[mf], B[0][0], B[0][1]);
                    mma16(acc[mf][1], A[mf], B[0][2], B[0][3]);
                    mma16(acc[mf][2], A[mf], B[1][0], B[1][1]);
                    mma16(acc[mf][3], A[mf], B[1][2], B[1][3]);
                }
            }
        }

        if (kl < NITER && a_act) {   // stage prefetched A tile
            *(uint4*)(smem + pslot + ast0) =
                make_uint4(pack_h2(f0.x, f0.y), pack_h2(f0.z, f0.w),
                           pack_h2(f1.x, f1.y), pack_h2(f1.z, f1.w));
            *(uint4*)(smem + pslot + ast1) =
                make_uint4(pack_h2(f2.x, f2.y), pack_h2(f2.z, f2.w),
                           pack_h2(f3.x, f3.y), pack_h2(f3.z, f3.w));
        }
        asm volatile("cp.async.wait_group %0;" :: "n"(STAGES - 2) : "memory");
        __syncthreads();
    }
}

// ---------------------------------------------------------------- GEMM body for one M-unit (MROWS = MFRAGS*16, 112 or 96)
// Warp map: m_off = (wid>>2)*32, n_off = (wid&3)*32 -> every SMSP holds one
// warp of each M-group; trimming the tail frag offloads all SMSPs equally.
// The frag-count choice is made ONCE (warp-uniform) before the mainloop; the
// three mainloop instantiations are branch-free inside.
template <int PASS, int MFRAGS>
DI void gemm_body(const float* __restrict__ adj, const __half* __restrict__ BT,
                  const float* __restrict__ bias, const float* __restrict__ W2,
                  const float* __restrict__ bl, float* __restrict__ OUT,
                  __half* __restrict__ OUTH, int m_start, char* smem, uint32_t sb) {
    constexpr int MROWS = MFRAGS * 16;
    int tid = threadIdx.x, wid = tid >> 5, lane = tid & 31;

    // preload epilogue weights + bias (region disjoint from stages)
    {
        float* Wsm = (float*)(smem + SM_W);
        if (PASS == 1) {
            for (int e = tid; e < 64 * 64; e += 512)        // W1^T: Wsm[j*64+c]=W1[c][j]
                Wsm[e] = W2[(e & 63) * 64 + (e >> 6)];
        } else {
            for (int e = tid; e < 128 * 32; e += 512)       // Wl^T: Wsm[j*32+o]=Wl[o][j]
                Wsm[e] = W2[(e & 31) * 128 + (e >> 5)];
        }
        float* bsm = (float*)(smem + SM_BS);
        if (tid < 128) bsm[tid] = bias[tid & 63];
    }

    // A staging (fp32->fp16): 4 threads/row, 16 floats each; only rows < MROWS
    int arid = tid >> 2;                 // 0..127
    int aseg = tid & 3;
    bool a_act = arid < MROWS;
    const float* agbase = adj + (size_t)(m_start + arid) * NN + aseg * 16;
    uint32_t ast0 = sw128((uint32_t)(arid * 128 + aseg * 32));
    uint32_t ast1 = sw128((uint32_t)(arid * 128 + aseg * 32 + 16));

    // B staging: 2 x 16B chunks per thread (1024 chunks: r=chunk>>3, c=chunk&7)
    int bc0 = tid, bc1 = tid + 512;

    // warp fragment bases
    int m_off = (wid >> 2) * 32;
    int n_off = (wid & 3) * 32;
    int r8 = lane & 7;
    uint32_t arow[2];
#pragma unroll
    for (int mf = 0; mf < 2; mf++)
        arow[mf] = (uint32_t)((m_off + mf * 16 + r8 + ((lane >> 3) & 1) * 8) * 128);
    uint32_t acolsel = (uint32_t)(((lane >> 4) & 1) * 16);
    uint32_t brow[2];
#pragma unroll
    for (int p = 0; p < 2; p++)
        brow[p] = (uint32_t)((n_off + p * 16 + r8 + ((lane >> 4) & 1) * 8) * 128);
    uint32_t bcolsel = (uint32_t)(((lane >> 3) & 1) * 16);

    int nf_act = 0;                      // warp-uniform active frag count
    if ((m_off >> 4) + 0 < MFRAGS) nf_act++;
    if ((m_off >> 4) + 1 < MFRAGS) nf_act++;

    float acc[2][4][4];
#pragma unroll
    for (int mf = 0; mf < 2; mf++)
#pragma unroll
        for (int nf = 0; nf < 4; nf++)
#pragma unroll
            for (int r = 0; r < 4; r++) acc[mf][nf][r] = 0.f;

    // ---- prologue: fully stage tiles 0..STAGES-2
#pragma unroll
    for (int p = 0; p < STAGES - 1; p++) {
        uint32_t abo = (uint32_t)p * STAGE_BYTES;
        if (a_act) {
            const float* ag = agbase + (size_t)p * KTILE;
            float4 f0 = ((const float4*)ag)[0], f1 = ((const float4*)ag)[1];
            float4 f2 = ((const float4*)ag)[2], f3 = ((const float4*)ag)[3];
            *(uint4*)(smem + abo + ast0) =
                make_uint4(pack_h2(f0.x, f0.y), pack_h2(f0.z, f0.w),
                           pack_h2(f1.x, f1.y), pack_h2(f1.z, f1.w));
            *(uint4*)(smem + abo + ast1) =
                make_uint4(pack_h2(f2.x, f2.y), pack_h2(f2.z, f2.w),
                           pack_h2(f3.x, f3.y), pack_h2(f3.z, f3.w));
        }
        uint32_t bb = sb + abo + 16384;
        int r = bc0 >> 3, c = bc0 & 7;
        cpa16(bb + sw128((uint32_t)(r * 128 + c * 16)),
              BT + (size_t)r * NN + (size_t)p * KTILE + c * 8);
        r = bc1 >> 3; c = bc1 & 7;
        cpa16(bb + sw128((uint32_t)(r * 128 + c * 16)),
              BT + (size_t)r * NN + (size_t)p * KTILE + c * 8);
        asm volatile("cp.async.commit_group;" ::: "memory");
    }
    asm volatile("cp.async.wait_group %0;" :: "n"(STAGES - 2) : "memory");
    __syncthreads();   // stage 0 ready (covers A STS + Wsm/bsm)

    // ---- mainloop: ONE warp-uniform branch, straight-line bodies
    if (nf_act == 2)
        mainloop_run<2>(agbase, BT, smem, sb, a_act, bc0, bc1, ast0, ast1,
                        arow, acolsel, brow, bcolsel, acc);
    else if (nf_act == 1)
        mainloop_run<1>(agbase, BT, smem, sb, a_act, bc0, bc1, ast0, ast1,
                        arow, acolsel, brow, bcolsel, acc);
    else
        mainloop_run<0>(agbase, BT, smem, sb, a_act, bc0, bc1, ast0, ast1,
                        arow, acolsel, brow, bcolsel, acc);

    // ---- epilogue phase 1: accum -> elu(+bias) -> Hs smem (pitch 129)
    float* Hs = (float*)smem;            // reuses stage region
    float* bsm = (float*)(smem + SM_BS);
#pragma unroll
    for (int mf = 0; mf < 2; mf++) {
        if ((m_off >> 4) + mf < MFRAGS) {
#pragma unroll
            for (int nf = 0; nf < 4; nf++)
#pragma unroll
                for (int r = 0; r < 4; r++) {
                    int row = m_off + mf * 16 + (lane >> 2) + ((r >> 1) << 3);
                    int col = n_off + nf * 8 + ((lane & 3) << 1) + (r & 1);
                    Hs[row * 129 + col] = eluf(acc[mf][nf][r] + bsm[col]);
                }
        }
    }
    __syncthreads();

    // ---- epilogue phase 2
    float* Wsm = (float*)(smem + SM_W);
    if (PASS == 1) {
        // X1T[ho+jj][m_start+i] = dot(Hs[i][ho..ho+64), W1 col jj)
        int i = tid & 127;
        int part = tid >> 7;
        if (i < MROWS) {
            int ho = (part & 1) * 64;
            int j0 = (part >> 1) * 32;
            float h[64];
#pragma unroll
            for (int c = 0; c < 64; c++) h[c] = Hs[i * 129 + ho + c];
            for (int jj = j0; jj < j0 + 32; jj++) {
                const float4* wr = (const float4*)(Wsm + jj * 64);
                float a = 0.f;
#pragma unroll
                for (int q = 0; q < 16; q++) {
                    float4 w = wr[q];
                    a += h[4 * q] * w.x + h[4 * q + 1] * w.y + h[4 * q + 2] * w.z + h[4 * q + 3] * w.w;
                }
                OUTH[(size_t)(ho + jj) * NN + m_start + i] = __float2half_rn(a);
            }
        }
    } else {
        // out[m_start+r][o] = bl[o] + sum_j Hs[r][j] * Wl[o][j]
        int r = tid >> 2;
        int og = (tid & 3) << 3;
        if (r < MROWS) {
            float a[8];
#pragma unroll
            for (int o = 0; o < 8; o++) a[o] = __ldg(bl + og + o);
            for (int j = 0; j < 128; j++) {
                float hv = Hs[r * 129 + j];
                const float4* wr = (const float4*)(Wsm + j * 32 + og);
#pragma unroll
                for (int q = 0; q < 2; q++) {
                    float4 w = wr[q];
                    a[4 * q + 0] += hv * w.x;
                    a[4 * q + 1] += hv * w.y;
                    a[4 * q + 2] += hv * w.z;
                    a[4 * q + 3] += hv * w.w;
                }
            }
            float4* op = (float4*)(OUT + (size_t)(m_start + r) * 32 + og);
#pragma unroll
            for (int q = 0; q < 2; q++)
                op[q] = make_float4(a[4 * q], a[4 * q + 1], a[4 * q + 2], a[4 * q + 3]);
        }
    }
}

template <int PASS>
__global__ void __launch_bounds__(512, 1) gemm_kernel(const float* __restrict__ adj,
                                                      const __half* __restrict__ BT,
                                                      const float* __restrict__ bias,
                                                      const float* __restrict__ W2,
                                                      const float* __restrict__ bl,
                                                      float* __restrict__ OUT,
                                                      __half* __restrict__ OUTH,
                                                      int abig) {
    extern __shared__ char smem[];
    uint32_t sb = smem_u32(smem);
    int bid = blockIdx.x;
    if (bid < abig)
        gemm_body<PASS, 7>(adj, BT, bias, W2, bl, OUT, OUTH, bid * 112, smem, sb);
    else
        gemm_body<PASS, 6>(adj, BT, bias, W2, bl, OUT, OUTH,
                           abig * 112 + (bid - abig) * 96, smem, sb);
}

// ---------------------------------------------------------------- launch
extern "C" void kernel_launch(void* const* d_in, const int* in_sizes, int n_in,
                              void* d_out, int out_size) {
    const float* z   = (const float*)d_in[0];
    const float* adj = (const float*)d_in[1];
    const float* W0  = (const float*)d_in[2];
    const float* b0  = (const float*)d_in[3];
    const float* W1  = (const float*)d_in[4];
    const float* b1  = (const float*)d_in[5];
    const float* Wl  = (const float*)d_in[6];
    const float* bl  = (const float*)d_in[7];
    float* out = (float*)d_out;

    __half *x0t = nullptr, *x1t = nullptr;
    cudaGetSymbolAddress((void**)&x0t, g_X0T);
    cudaGetSymbolAddress((void**)&x1t, g_X1T);

    // one CTA per SM, single wave: abig x 112 rows + (grid-abig) x 96 rows == 16384
    int dev = 0, nsm = 148;
    cudaGetDevice(&dev);
    cudaDeviceGetAttribute(&nsm, cudaDevAttrMultiProcessorCount, dev);
    if (nsm < 147) nsm = 147;
    if (nsm > 170) nsm = 170;
    int grid = nsm;
    int abig = 1024 - 6 * nsm;           // 112*abig + 96*(grid-abig) = 16384

    cudaFuncSetAttribute(prep_kernel, cudaFuncAttributeMaxDynamicSharedMemorySize, PREP_SMEM);
    cudaFuncSetAttribute(gemm_kernel<1>, cudaFuncAttributeMaxDynamicSharedMemorySize, GEMM_SMEM);
    cudaFuncSetAttribute(gemm_kernel<2>, cudaFuncAttributeMaxDynamicSharedMemorySize, GEMM_SMEM);

    prep_kernel<<<NN / 128, 512, PREP_SMEM>>>(z, W0, x0t);
    gemm_kernel<1><<<grid, 512, GEMM_SMEM>>>(adj, x0t, b0, W1, nullptr, nullptr, x1t, abig);
    gemm_kernel<2><<<grid, 512, GEMM_SMEM>>>(adj, x1t, b1, Wl, bl, out, nullptr, abig);
}